// round 1
// baseline (speedup 1.0000x reference)
#include <cuda_runtime.h>
#include <math.h>

// Problem constants (fixed by the reference setup_inputs)
#define BATCH_M   16384   // B*S = 32*512
#define DIM_D     768
#define DIM_N     2304    // 3*D
#define NUM_T     10
#define RANK_R    16
#define SEG       (RANK_R * DIM_D)  // 12288 elems per task per adapter matrix

// Device scratch (no cudaMalloc allowed)
__device__ float g_sumsq[40];              // [Aq(10) | Bq(10) | Av(10) | Bv(10)]
__device__ float g_wq[NUM_T];
__device__ float g_wv[NUM_T];
__device__ float g_weff[DIM_N * DIM_D];    // fused weight, row-major [2304][768]

// ---------------------------------------------------------------------------
// Kernel 1: per-task Frobenius sum-of-squares for the 4 adapter tensors.
// One block per (tensor, task) pair: 40 blocks x 256 threads.
// ---------------------------------------------------------------------------
__global__ void k_sumsq(const float* __restrict__ Aq, const float* __restrict__ Bq,
                        const float* __restrict__ Av, const float* __restrict__ Bv) {
    int b = blockIdx.x;                 // 0..39
    const float* base;
    switch (b / NUM_T) {
        case 0:  base = Aq; break;
        case 1:  base = Bq; break;
        case 2:  base = Av; break;
        default: base = Bv; break;
    }
    base += (b % NUM_T) * SEG;

    float s = 0.f;
    for (int i = threadIdx.x; i < SEG; i += blockDim.x) {
        float v = base[i];
        s += v * v;
    }
    __shared__ float red[256];
    red[threadIdx.x] = s;
    __syncthreads();
    for (int o = 128; o > 0; o >>= 1) {
        if (threadIdx.x < o) red[threadIdx.x] += red[threadIdx.x + o];
        __syncthreads();
    }
    if (threadIdx.x == 0) g_sumsq[b] = red[0];
}

// ---------------------------------------------------------------------------
// Kernel 2: softmax gate + fold alpha and norms into per-task weights.
// Tiny: one thread does everything (T = 10).
// ---------------------------------------------------------------------------
__global__ void k_weights(const float* __restrict__ logits,
                          const float* __restrict__ alpha) {
    if (threadIdx.x == 0 && blockIdx.x == 0) {
        float mx = -1e30f;
        for (int t = 0; t < NUM_T; t++) mx = fmaxf(mx, logits[t]);
        float e[NUM_T], se = 0.f;
        for (int t = 0; t < NUM_T; t++) { e[t] = expf(logits[t] - mx); se += e[t]; }
        for (int t = 0; t < NUM_T; t++) {
            float coef = (e[t] / se) * alpha[t];
            g_wq[t] = coef / (sqrtf(g_sumsq[t])      * sqrtf(g_sumsq[10 + t]) + 1e-8f);
            g_wv[t] = coef / (sqrtf(g_sumsq[20 + t]) * sqrtf(g_sumsq[30 + t]) + 1e-8f);
        }
    }
}

// ---------------------------------------------------------------------------
// Kernel 3: build fused weight W_eff[e][d] = qkv_w[e][d] (+ LoRA delta).
//   rows e in [0,768):      += sum_{t,r} wq[t] * B_q[t,e,r]    * A_q[t,r,d]
//   rows e in [1536,2304):  += sum_{t,r} wv[t] * B_v[t,e-1536,r]* A_v[t,r,d]
// Grid: (768/256, 2304). Block handles one e-row, 256 d-columns.
// ---------------------------------------------------------------------------
__global__ void k_weff(const float* __restrict__ Aq, const float* __restrict__ Bq,
                       const float* __restrict__ Av, const float* __restrict__ Bv,
                       const float* __restrict__ qkvw) {
    int e = blockIdx.y;
    int d = blockIdx.x * 256 + threadIdx.x;

    __shared__ float sB[NUM_T * RANK_R];   // 160 weighted B values for this e-row

    float val = qkvw[e * DIM_D + d];

    bool is_q = (e < DIM_D);
    bool is_v = (e >= 2 * DIM_D);
    if (is_q || is_v) {
        const float* Am = is_q ? Aq : Av;
        const float* Bm = is_q ? Bq : Bv;
        int el = is_q ? e : (e - 2 * DIM_D);
        if (threadIdx.x < NUM_T * RANK_R) {
            int t = threadIdx.x >> 4;
            int r = threadIdx.x & 15;
            float w = is_q ? g_wq[t] : g_wv[t];
            sB[threadIdx.x] = w * Bm[(t * DIM_D + el) * RANK_R + r];
        }
        __syncthreads();
        float acc = 0.f;
        #pragma unroll 8
        for (int i = 0; i < NUM_T * RANK_R; i++)
            acc += sB[i] * Am[i * DIM_D + d];   // A[t,r,d] with i = t*16+r
        val += acc;
    }
    g_weff[e * DIM_D + d] = val;
}

// ---------------------------------------------------------------------------
// Kernel 4: main GEMM  out[M,N] = X[M,K] @ W_eff[N,K]^T + bias[N]
// 128x128 CTA tile, BK=16, 256 threads, 8x8 per-thread register tile.
// ---------------------------------------------------------------------------
#define BM 128
#define BN 128
#define BKK 16
#define SPAD 4

__global__ __launch_bounds__(256, 2)
void k_gemm(const float* __restrict__ X, const float* __restrict__ bias,
            float* __restrict__ out) {
    __shared__ float As[BKK][BM + SPAD];
    __shared__ float Bs[BKK][BN + SPAD];

    const int m0 = blockIdx.y * BM;
    const int n0 = blockIdx.x * BN;
    const int tid = threadIdx.x;
    const float* __restrict__ W = g_weff;

    float acc[8][8];
    #pragma unroll
    for (int i = 0; i < 8; i++)
        #pragma unroll
        for (int j = 0; j < 8; j++) acc[i][j] = 0.f;

    const int ty = tid >> 4;   // 0..15, M direction
    const int tx = tid & 15;   // 0..15, N direction

    for (int k0 = 0; k0 < DIM_D; k0 += BKK) {
        // Stage tiles: 512 float4 per operand, 2 per thread per operand.
        #pragma unroll
        for (int h = 0; h < 2; h++) {
            int v   = tid + h * 256;      // 0..511
            int row = v >> 2;             // 0..127
            int c4  = (v & 3) * 4;        // 0,4,8,12
            float4 a = *(const float4*)(X + (long)(m0 + row) * DIM_D + k0 + c4);
            As[c4 + 0][row] = a.x; As[c4 + 1][row] = a.y;
            As[c4 + 2][row] = a.z; As[c4 + 3][row] = a.w;
            float4 b = *(const float4*)(W + (long)(n0 + row) * DIM_D + k0 + c4);
            Bs[c4 + 0][row] = b.x; Bs[c4 + 1][row] = b.y;
            Bs[c4 + 2][row] = b.z; Bs[c4 + 3][row] = b.w;
        }
        __syncthreads();

        #pragma unroll
        for (int kk = 0; kk < BKK; kk++) {
            float a[8], b[8];
            *(float4*)(a)     = *(const float4*)&As[kk][ty * 8];
            *(float4*)(a + 4) = *(const float4*)&As[kk][ty * 8 + 4];
            *(float4*)(b)     = *(const float4*)&Bs[kk][tx * 8];
            *(float4*)(b + 4) = *(const float4*)&Bs[kk][tx * 8 + 4];
            #pragma unroll
            for (int i = 0; i < 8; i++)
                #pragma unroll
                for (int j = 0; j < 8; j++)
                    acc[i][j] += a[i] * b[j];
        }
        __syncthreads();
    }

    // Epilogue: add bias, vectorized stores.
    const int n = n0 + tx * 8;
    float bj[8];
    #pragma unroll
    for (int j = 0; j < 8; j++) bj[j] = bias[n + j];

    #pragma unroll
    for (int i = 0; i < 8; i++) {
        long m = m0 + ty * 8 + i;
        float4 o0 = make_float4(acc[i][0] + bj[0], acc[i][1] + bj[1],
                                acc[i][2] + bj[2], acc[i][3] + bj[3]);
        float4 o1 = make_float4(acc[i][4] + bj[4], acc[i][5] + bj[5],
                                acc[i][6] + bj[6], acc[i][7] + bj[7]);
        *(float4*)(out + m * DIM_N + n)     = o0;
        *(float4*)(out + m * DIM_N + n + 4) = o1;
    }
}

// ---------------------------------------------------------------------------
// Launch: inputs in metadata order:
//   0:x 1:A_q 2:B_q 3:A_v 4:B_v 5:qkv_w 6:qkv_b 7:gate_logits 8:alpha
// ---------------------------------------------------------------------------
extern "C" void kernel_launch(void* const* d_in, const int* in_sizes, int n_in,
                              void* d_out, int out_size) {
    const float* x      = (const float*)d_in[0];
    const float* Aq     = (const float*)d_in[1];
    const float* Bq     = (const float*)d_in[2];
    const float* Av     = (const float*)d_in[3];
    const float* Bv     = (const float*)d_in[4];
    const float* qkvw   = (const float*)d_in[5];
    const float* qkvb   = (const float*)d_in[6];
    const float* logits = (const float*)d_in[7];
    const float* alpha  = (const float*)d_in[8];
    float* out = (float*)d_out;

    k_sumsq  <<<40, 256>>>(Aq, Bq, Av, Bv);
    k_weights<<<1, 32>>>(logits, alpha);
    k_weff   <<<dim3(DIM_D / 256, DIM_N), 256>>>(Aq, Bq, Av, Bv, qkvw);
    k_gemm   <<<dim3(DIM_N / BN, BATCH_M / BM), 256>>>(x, qkvb, out);
}

// round 3
// speedup vs baseline: 2.3434x; 2.3434x over previous
#include <cuda_runtime.h>
#include <cuda_bf16.h>
#include <math.h>
#include <stdint.h>

// Problem constants
#define BATCH_M   16384   // B*S
#define DIM_D     768
#define DIM_N     2304    // 3*D
#define NUM_T     10
#define RANK_R    16
#define SEG       (RANK_R * DIM_D)

// GEMM tiling
#define BM 128
#define BN 128
#define BK 32                      // bf16 elems per K stage
#define KSTAGES (DIM_D / BK)       // 24

// SMEM layout: rows padded to 80B for conflict-free ldmatrix
#define ROWB     80
#define OFF_ALO  10240             // 128 rows * 80B
#define OFF_BHI  20480
#define OFF_BLO  30720
#define STAGEB   40960
#define SMEM_TOTAL (2 * STAGEB)

// Device scratch (no cudaMalloc allowed)
__device__ float g_sumsq[40];
__device__ float g_wq[NUM_T];
__device__ float g_wv[NUM_T];
__device__ unsigned short g_Xhi[(size_t)BATCH_M * DIM_D];
__device__ unsigned short g_Xlo[(size_t)BATCH_M * DIM_D];
__device__ unsigned short g_Whi[(size_t)DIM_N * DIM_D];
__device__ unsigned short g_Wlo[(size_t)DIM_N * DIM_D];

// ---------------------------------------------------------------------------
// Helpers
// ---------------------------------------------------------------------------
__device__ __forceinline__ uint32_t smem_u32(const void* p) {
    uint32_t a;
    asm("{ .reg .u64 t; cvta.to.shared.u64 t, %1; cvt.u32.u64 %0, t; }" : "=r"(a) : "l"(p));
    return a;
}
#define CP16(dst, src) \
    asm volatile("cp.async.cg.shared.global [%0], [%1], 16;" :: "r"(dst), "l"(src))
#define CP_COMMIT() asm volatile("cp.async.commit_group;" ::: "memory")
#define CP_WAIT1()  asm volatile("cp.async.wait_group 1;"  ::: "memory")
#define CP_WAIT0()  asm volatile("cp.async.wait_group 0;"  ::: "memory")

__device__ __forceinline__ void ldsm_x4(uint32_t* r, uint32_t addr) {
    asm volatile("ldmatrix.sync.aligned.m8n8.x4.shared.b16 {%0,%1,%2,%3}, [%4];"
        : "=r"(r[0]), "=r"(r[1]), "=r"(r[2]), "=r"(r[3]) : "r"(addr));
}
__device__ __forceinline__ void mma_bf16(float* c, const uint32_t* a,
                                         uint32_t b0, uint32_t b1) {
    asm volatile("mma.sync.aligned.m16n8k16.row.col.f32.bf16.bf16.f32 "
        "{%0,%1,%2,%3},{%4,%5,%6,%7},{%8,%9},{%0,%1,%2,%3};"
        : "+f"(c[0]), "+f"(c[1]), "+f"(c[2]), "+f"(c[3])
        : "r"(a[0]), "r"(a[1]), "r"(a[2]), "r"(a[3]), "r"(b0), "r"(b1));
}

__device__ __forceinline__ void split_f32(float v, unsigned short& h, unsigned short& l) {
    __nv_bfloat16 hb = __float2bfloat16(v);
    float r = v - __bfloat162float(hb);
    __nv_bfloat16 lb = __float2bfloat16(r);
    h = __bfloat16_as_ushort(hb);
    l = __bfloat16_as_ushort(lb);
}

// ---------------------------------------------------------------------------
// Kernel 1: per-task Frobenius sum-of-squares
// ---------------------------------------------------------------------------
__global__ void k_sumsq(const float* __restrict__ Aq, const float* __restrict__ Bq,
                        const float* __restrict__ Av, const float* __restrict__ Bv) {
    int b = blockIdx.x;
    const float* base;
    switch (b / NUM_T) {
        case 0:  base = Aq; break;
        case 1:  base = Bq; break;
        case 2:  base = Av; break;
        default: base = Bv; break;
    }
    base += (b % NUM_T) * SEG;
    float s = 0.f;
    for (int i = threadIdx.x; i < SEG; i += blockDim.x) {
        float v = base[i];
        s += v * v;
    }
    __shared__ float red[256];
    red[threadIdx.x] = s;
    __syncthreads();
    for (int o = 128; o > 0; o >>= 1) {
        if (threadIdx.x < o) red[threadIdx.x] += red[threadIdx.x + o];
        __syncthreads();
    }
    if (threadIdx.x == 0) g_sumsq[b] = red[0];
}

// ---------------------------------------------------------------------------
// Kernel 2: softmax gate + fold alpha / norms into per-task weights
// ---------------------------------------------------------------------------
__global__ void k_weights(const float* __restrict__ logits,
                          const float* __restrict__ alpha) {
    if (threadIdx.x == 0 && blockIdx.x == 0) {
        float mx = -1e30f;
        for (int t = 0; t < NUM_T; t++) mx = fmaxf(mx, logits[t]);
        float e[NUM_T], se = 0.f;
        for (int t = 0; t < NUM_T; t++) { e[t] = expf(logits[t] - mx); se += e[t]; }
        for (int t = 0; t < NUM_T; t++) {
            float coef = (e[t] / se) * alpha[t];
            g_wq[t] = coef / (sqrtf(g_sumsq[t])      * sqrtf(g_sumsq[10 + t]) + 1e-8f);
            g_wv[t] = coef / (sqrtf(g_sumsq[20 + t]) * sqrtf(g_sumsq[30 + t]) + 1e-8f);
        }
    }
}

// ---------------------------------------------------------------------------
// Kernel 3: build fused weight W_eff, emit bf16 hi/lo split
// ---------------------------------------------------------------------------
__global__ void k_weff(const float* __restrict__ Aq, const float* __restrict__ Bq,
                       const float* __restrict__ Av, const float* __restrict__ Bv,
                       const float* __restrict__ qkvw) {
    int e = blockIdx.y;
    int d = blockIdx.x * 256 + threadIdx.x;

    __shared__ float sB[NUM_T * RANK_R];
    float val = qkvw[e * DIM_D + d];

    bool is_q = (e < DIM_D);
    bool is_v = (e >= 2 * DIM_D);
    if (is_q || is_v) {
        const float* Am = is_q ? Aq : Av;
        const float* Bm = is_q ? Bq : Bv;
        int el = is_q ? e : (e - 2 * DIM_D);
        if (threadIdx.x < NUM_T * RANK_R) {
            int t = threadIdx.x >> 4;
            int r = threadIdx.x & 15;
            float w = is_q ? g_wq[t] : g_wv[t];
            sB[threadIdx.x] = w * Bm[(t * DIM_D + el) * RANK_R + r];
        }
        __syncthreads();
        float acc = 0.f;
        #pragma unroll 8
        for (int i = 0; i < NUM_T * RANK_R; i++)
            acc += sB[i] * Am[i * DIM_D + d];
        val += acc;
    }
    unsigned short h, l;
    split_f32(val, h, l);
    g_Whi[e * DIM_D + d] = h;
    g_Wlo[e * DIM_D + d] = l;
}

// ---------------------------------------------------------------------------
// Kernel 3b: split X into bf16 hi/lo
// ---------------------------------------------------------------------------
__global__ void k_convert_x(const float* __restrict__ x) {
    size_t i = ((size_t)blockIdx.x * blockDim.x + threadIdx.x) * 4;
    float4 v = *(const float4*)(x + i);
    unsigned short h0, h1, h2, h3, l0, l1, l2, l3;
    split_f32(v.x, h0, l0);
    split_f32(v.y, h1, l1);
    split_f32(v.z, h2, l2);
    split_f32(v.w, h3, l3);
    uint2 hh = make_uint2((uint32_t)h0 | ((uint32_t)h1 << 16),
                          (uint32_t)h2 | ((uint32_t)h3 << 16));
    uint2 ll = make_uint2((uint32_t)l0 | ((uint32_t)l1 << 16),
                          (uint32_t)l2 | ((uint32_t)l3 << 16));
    *(uint2*)(g_Xhi + i) = hh;
    *(uint2*)(g_Xlo + i) = ll;
}

// ---------------------------------------------------------------------------
// Kernel 4: HMMA GEMM  out[M,N] = Xsplit @ Wsplit^T + bias
//   128x128 CTA tile, BK=32, cp.async double buffer, mma.sync bf16,
//   3 split products (hi*hi + lo*hi + hi*lo) into one fp32 accumulator.
// ---------------------------------------------------------------------------
__global__ __launch_bounds__(256, 2)
void k_gemm_mma(const float* __restrict__ bias, float* __restrict__ out) {
    extern __shared__ __align__(128) char smem[];
    const uint32_t sb = smem_u32(smem);
    const int tid = threadIdx.x;
    const int lid = tid & 31;
    const int wid = tid >> 5;
    const int wm = wid & 3;          // 4 warps in M, 32 rows each
    const int wn = wid >> 2;         // 2 warps in N, 64 cols each
    const int m0 = blockIdx.y * BM;
    const int n0 = blockIdx.x * BN;

    float acc[2][8][4];
    #pragma unroll
    for (int i = 0; i < 2; i++)
        #pragma unroll
        for (int j = 0; j < 8; j++)
            #pragma unroll
            for (int q = 0; q < 4; q++) acc[i][j][q] = 0.f;

    // per-lane ldmatrix offsets
    const uint32_t a_off = (uint32_t)(lid & 15) * ROWB + (uint32_t)(lid >> 4) * 16;
    const int b_nloc = (lid < 16) ? (lid & 7) : 8 + (lid & 7);
    const uint32_t b_off = (uint32_t)b_nloc * ROWB + (uint32_t)((lid >> 3) & 1) * 16;

    // stage loader: 8 cp.async of 16B per thread
    auto load_stage = [&](int s) {
        uint32_t buf = sb + (uint32_t)(s & 1) * STAGEB;
        int k0 = s * BK;
        #pragma unroll
        for (int i = 0; i < 2; i++) {
            int v = tid + i * 256;
            int r = v >> 2, c = v & 3;
            uint32_t d = buf + (uint32_t)r * ROWB + (uint32_t)c * 16;
            size_t xi = (size_t)(m0 + r) * DIM_D + k0 + c * 8;
            size_t wi = (size_t)(n0 + r) * DIM_D + k0 + c * 8;
            CP16(d,           g_Xhi + xi);
            CP16(d + OFF_ALO, g_Xlo + xi);
            CP16(d + OFF_BHI, g_Whi + wi);
            CP16(d + OFF_BLO, g_Wlo + wi);
        }
    };

    load_stage(0);
    CP_COMMIT();

    for (int s = 0; s < KSTAGES; s++) {
        if (s + 1 < KSTAGES) {
            load_stage(s + 1);
            CP_COMMIT();
            CP_WAIT1();
        } else {
            CP_WAIT0();
        }
        __syncthreads();

        uint32_t buf = sb + (uint32_t)(s & 1) * STAGEB;
        #pragma unroll
        for (int kk = 0; kk < 2; kk++) {
            uint32_t ra_hi[2][4], ra_lo[2][4], rb[4][4];
            uint32_t koff = (uint32_t)kk * 32;
            #pragma unroll
            for (int mt = 0; mt < 2; mt++) {
                uint32_t arow = (uint32_t)(wm * 32 + mt * 16) * ROWB + koff + a_off;
                ldsm_x4(ra_hi[mt], buf + arow);
                ldsm_x4(ra_lo[mt], buf + OFF_ALO + arow);
            }
            // B hi
            #pragma unroll
            for (int ng = 0; ng < 4; ng++)
                ldsm_x4(rb[ng], buf + OFF_BHI + (uint32_t)(wn * 64 + ng * 16) * ROWB + koff + b_off);
            #pragma unroll
            for (int mt = 0; mt < 2; mt++)
                #pragma unroll
                for (int nt = 0; nt < 8; nt++) {
                    uint32_t b0 = rb[nt >> 1][(nt & 1) * 2];
                    uint32_t b1 = rb[nt >> 1][(nt & 1) * 2 + 1];
                    mma_bf16(acc[mt][nt], ra_hi[mt], b0, b1);   // hi*hi
                }
            #pragma unroll
            for (int mt = 0; mt < 2; mt++)
                #pragma unroll
                for (int nt = 0; nt < 8; nt++) {
                    uint32_t b0 = rb[nt >> 1][(nt & 1) * 2];
                    uint32_t b1 = rb[nt >> 1][(nt & 1) * 2 + 1];
                    mma_bf16(acc[mt][nt], ra_lo[mt], b0, b1);   // lo*hi
                }
            // B lo (reuse rb registers)
            #pragma unroll
            for (int ng = 0; ng < 4; ng++)
                ldsm_x4(rb[ng], buf + OFF_BLO + (uint32_t)(wn * 64 + ng * 16) * ROWB + koff + b_off);
            #pragma unroll
            for (int mt = 0; mt < 2; mt++)
                #pragma unroll
                for (int nt = 0; nt < 8; nt++) {
                    uint32_t b0 = rb[nt >> 1][(nt & 1) * 2];
                    uint32_t b1 = rb[nt >> 1][(nt & 1) * 2 + 1];
                    mma_bf16(acc[mt][nt], ra_hi[mt], b0, b1);   // hi*lo
                }
        }
        __syncthreads();
    }

    // Epilogue: bias add + float2 stores
    const int r0 = m0 + wm * 32 + (lid >> 2);
    const int cb = n0 + wn * 64 + (lid & 3) * 2;
    #pragma unroll
    for (int nt = 0; nt < 8; nt++) {
        float2 bv = *(const float2*)(bias + cb + nt * 8);
        #pragma unroll
        for (int mt = 0; mt < 2; mt++) {
            int r = r0 + mt * 16;
            float2 v0 = make_float2(acc[mt][nt][0] + bv.x, acc[mt][nt][1] + bv.y);
            float2 v1 = make_float2(acc[mt][nt][2] + bv.x, acc[mt][nt][3] + bv.y);
            *(float2*)(out + (size_t)r * DIM_N + cb + nt * 8) = v0;
            *(float2*)(out + (size_t)(r + 8) * DIM_N + cb + nt * 8) = v1;
        }
    }
}

// ---------------------------------------------------------------------------
// Launch
// ---------------------------------------------------------------------------
extern "C" void kernel_launch(void* const* d_in, const int* in_sizes, int n_in,
                              void* d_out, int out_size) {
    const float* x      = (const float*)d_in[0];
    const float* Aq     = (const float*)d_in[1];
    const float* Bq     = (const float*)d_in[2];
    const float* Av     = (const float*)d_in[3];
    const float* Bv     = (const float*)d_in[4];
    const float* qkvw   = (const float*)d_in[5];
    const float* qkvb   = (const float*)d_in[6];
    const float* logits = (const float*)d_in[7];
    const float* alpha  = (const float*)d_in[8];
    float* out = (float*)d_out;

    cudaFuncSetAttribute(k_gemm_mma, cudaFuncAttributeMaxDynamicSharedMemorySize, SMEM_TOTAL);

    k_sumsq    <<<40, 256>>>(Aq, Bq, Av, Bv);
    k_weights  <<<1, 32>>>(logits, alpha);
    k_convert_x<<<(BATCH_M * DIM_D / 4) / 256, 256>>>(x);
    k_weff     <<<dim3(DIM_D / 256, DIM_N), 256>>>(Aq, Bq, Av, Bv, qkvw);
    k_gemm_mma <<<dim3(DIM_N / BN, BATCH_M / BM), 256, SMEM_TOTAL>>>(qkvb, out);
}

// round 4
// speedup vs baseline: 3.2183x; 1.3733x over previous
#include <cuda_runtime.h>
#include <cuda_fp16.h>
#include <math.h>
#include <stdint.h>

// Problem constants
#define BATCH_M   16384   // B*S
#define DIM_D     768
#define DIM_N     2304    // 3*D
#define NUM_T     10
#define RANK_R    16
#define SEG       (RANK_R * DIM_D)

// GEMM tiling
#define BM 128
#define BN 128
#define BK 32                      // fp16 elems per K stage
#define KSTAGES (DIM_D / BK)       // 24

// SMEM: 3 arrays per stage (Ahi, Alo, Bhi), rows padded to 80B
#define ROWB     80
#define ARRB     10240             // 128 rows * 80B
#define STAGEB   30720
#define NSTAGE   3
#define SMEM_TOTAL (NSTAGE * STAGEB)

// Device scratch (no cudaMalloc allowed)
__device__ float g_sumsq[40];
__device__ float g_wq[NUM_T];
__device__ float g_wv[NUM_T];
__device__ __align__(16) unsigned short g_Xhi[(size_t)BATCH_M * DIM_D];
__device__ __align__(16) unsigned short g_Xlo[(size_t)BATCH_M * DIM_D];
__device__ __align__(16) unsigned short g_Whi[(size_t)DIM_N * DIM_D];

// ---------------------------------------------------------------------------
// Helpers
// ---------------------------------------------------------------------------
__device__ __forceinline__ uint32_t smem_u32(const void* p) {
    uint32_t a;
    asm("{ .reg .u64 t; cvta.to.shared.u64 t, %1; cvt.u32.u64 %0, t; }" : "=r"(a) : "l"(p));
    return a;
}
#define CP16(dst, src) \
    asm volatile("cp.async.cg.shared.global [%0], [%1], 16;" :: "r"(dst), "l"(src))
#define CP_COMMIT() asm volatile("cp.async.commit_group;" ::: "memory")
#define CP_WAIT1()  asm volatile("cp.async.wait_group 1;"  ::: "memory")
#define CP_WAIT0()  asm volatile("cp.async.wait_group 0;"  ::: "memory")

__device__ __forceinline__ void ldsm_x4(uint32_t* r, uint32_t addr) {
    asm volatile("ldmatrix.sync.aligned.m8n8.x4.shared.b16 {%0,%1,%2,%3}, [%4];"
        : "=r"(r[0]), "=r"(r[1]), "=r"(r[2]), "=r"(r[3]) : "r"(addr));
}
__device__ __forceinline__ void mma_fp16(float* c, const uint32_t* a,
                                         uint32_t b0, uint32_t b1) {
    asm volatile("mma.sync.aligned.m16n8k16.row.col.f32.f16.f16.f32 "
        "{%0,%1,%2,%3},{%4,%5,%6,%7},{%8,%9},{%0,%1,%2,%3};"
        : "+f"(c[0]), "+f"(c[1]), "+f"(c[2]), "+f"(c[3])
        : "r"(a[0]), "r"(a[1]), "r"(a[2]), "r"(a[3]), "r"(b0), "r"(b1));
}

// ---------------------------------------------------------------------------
// Kernel 1: per-task Frobenius sum-of-squares
// ---------------------------------------------------------------------------
__global__ void k_sumsq(const float* __restrict__ Aq, const float* __restrict__ Bq,
                        const float* __restrict__ Av, const float* __restrict__ Bv) {
    int b = blockIdx.x;
    const float* base;
    switch (b / NUM_T) {
        case 0:  base = Aq; break;
        case 1:  base = Bq; break;
        case 2:  base = Av; break;
        default: base = Bv; break;
    }
    base += (b % NUM_T) * SEG;
    float s = 0.f;
    for (int i = threadIdx.x; i < SEG; i += blockDim.x) {
        float v = base[i];
        s += v * v;
    }
    __shared__ float red[256];
    red[threadIdx.x] = s;
    __syncthreads();
    for (int o = 128; o > 0; o >>= 1) {
        if (threadIdx.x < o) red[threadIdx.x] += red[threadIdx.x + o];
        __syncthreads();
    }
    if (threadIdx.x == 0) g_sumsq[b] = red[0];
}

// ---------------------------------------------------------------------------
// Kernel 2: softmax gate + fold alpha / norms into per-task weights
// ---------------------------------------------------------------------------
__global__ void k_weights(const float* __restrict__ logits,
                          const float* __restrict__ alpha) {
    if (threadIdx.x == 0 && blockIdx.x == 0) {
        float mx = -1e30f;
        for (int t = 0; t < NUM_T; t++) mx = fmaxf(mx, logits[t]);
        float e[NUM_T], se = 0.f;
        for (int t = 0; t < NUM_T; t++) { e[t] = expf(logits[t] - mx); se += e[t]; }
        for (int t = 0; t < NUM_T; t++) {
            float coef = (e[t] / se) * alpha[t];
            g_wq[t] = coef / (sqrtf(g_sumsq[t])      * sqrtf(g_sumsq[10 + t]) + 1e-8f);
            g_wv[t] = coef / (sqrtf(g_sumsq[20 + t]) * sqrtf(g_sumsq[30 + t]) + 1e-8f);
        }
    }
}

// ---------------------------------------------------------------------------
// Kernel 3: build fused weight W_eff -> fp16.
// Block = 128 threads, handles 16 e-rows x 128 d-cols. Weighted B staged in
// smem as [i][e] so the inner loop does 16 FMAs per single A load.
// ---------------------------------------------------------------------------
__global__ __launch_bounds__(128)
void k_weff(const float* __restrict__ Aq, const float* __restrict__ Bq,
            const float* __restrict__ Av, const float* __restrict__ Bv,
            const float* __restrict__ qkvw) {
    const int d  = blockIdx.x * 128 + threadIdx.x;
    const int e0 = blockIdx.y * 16;
    const int tx = threadIdx.x;

    float acc[16];
    #pragma unroll
    for (int e = 0; e < 16; e++) acc[e] = 0.f;

    bool is_q = (e0 < DIM_D);
    bool is_v = (e0 >= 2 * DIM_D);
    if (is_q || is_v) {
        __shared__ __align__(16) float sB[NUM_T * RANK_R * 16];  // [i][e]
        const float* Am = is_q ? Aq : Av;
        const float* Bm = is_q ? Bq : Bv;
        int el0 = is_q ? e0 : (e0 - 2 * DIM_D);
        // Fill weighted B: entry (i, e) = w[t] * B[t, el0+e, r], i = t*16+r
        for (int idx = tx; idx < NUM_T * RANK_R * 16; idx += 128) {
            int i = idx >> 4, e = idx & 15;
            int t = i >> 4,  r = i & 15;
            float w = is_q ? g_wq[t] : g_wv[t];
            sB[idx] = w * Bm[((size_t)t * DIM_D + el0 + e) * RANK_R + r];
        }
        __syncthreads();

        const float4* sB4 = (const float4*)sB;
        #pragma unroll 4
        for (int i = 0; i < NUM_T * RANK_R; i++) {
            float a = __ldg(Am + (size_t)i * DIM_D + d);
            float4 b0 = sB4[i * 4 + 0];
            float4 b1 = sB4[i * 4 + 1];
            float4 b2 = sB4[i * 4 + 2];
            float4 b3 = sB4[i * 4 + 3];
            acc[0]  += a * b0.x;  acc[1]  += a * b0.y;
            acc[2]  += a * b0.z;  acc[3]  += a * b0.w;
            acc[4]  += a * b1.x;  acc[5]  += a * b1.y;
            acc[6]  += a * b1.z;  acc[7]  += a * b1.w;
            acc[8]  += a * b2.x;  acc[9]  += a * b2.y;
            acc[10] += a * b2.z;  acc[11] += a * b2.w;
            acc[12] += a * b3.x;  acc[13] += a * b3.y;
            acc[14] += a * b3.z;  acc[15] += a * b3.w;
        }
    }
    #pragma unroll
    for (int e = 0; e < 16; e++) {
        float val = qkvw[(size_t)(e0 + e) * DIM_D + d] + acc[e];
        g_Whi[(size_t)(e0 + e) * DIM_D + d] = __half_as_ushort(__float2half(val));
    }
}

// ---------------------------------------------------------------------------
// Kernel 3b: split X into fp16 hi/lo (exact: xh + xl == x to 2^-22)
// ---------------------------------------------------------------------------
__global__ void k_convert_x(const float* __restrict__ x) {
    size_t i = ((size_t)blockIdx.x * blockDim.x + threadIdx.x) * 4;
    float4 v = *(const float4*)(x + i);
    __half h0 = __float2half(v.x), h1 = __float2half(v.y),
           h2 = __float2half(v.z), h3 = __float2half(v.w);
    __half l0 = __float2half(v.x - __half2float(h0));
    __half l1 = __float2half(v.y - __half2float(h1));
    __half l2 = __float2half(v.z - __half2float(h2));
    __half l3 = __float2half(v.w - __half2float(h3));
    uint2 hh = make_uint2((uint32_t)__half_as_ushort(h0) | ((uint32_t)__half_as_ushort(h1) << 16),
                          (uint32_t)__half_as_ushort(h2) | ((uint32_t)__half_as_ushort(h3) << 16));
    uint2 ll = make_uint2((uint32_t)__half_as_ushort(l0) | ((uint32_t)__half_as_ushort(l1) << 16),
                          (uint32_t)__half_as_ushort(l2) | ((uint32_t)__half_as_ushort(l3) << 16));
    *(uint2*)(g_Xhi + i) = hh;
    *(uint2*)(g_Xlo + i) = ll;
}

// ---------------------------------------------------------------------------
// Kernel 4: HMMA GEMM  out = (Xhi + Xlo) @ Whi^T + bias   (fp16, 2 products)
//   128x128 CTA tile, BK=32, 3-stage cp.async pipeline, 1 sync/stage.
// ---------------------------------------------------------------------------
__global__ __launch_bounds__(256, 2)
void k_gemm_mma(const float* __restrict__ bias, float* __restrict__ out) {
    extern __shared__ __align__(128) char smem[];
    const uint32_t sb = smem_u32(smem);
    const int tid = threadIdx.x;
    const int lid = tid & 31;
    const int wid = tid >> 5;
    const int wm = wid & 3;          // 4 warps in M, 32 rows each
    const int wn = wid >> 2;         // 2 warps in N, 64 cols each
    const int m0 = blockIdx.y * BM;
    const int n0 = blockIdx.x * BN;

    float acc[2][8][4];
    #pragma unroll
    for (int i = 0; i < 2; i++)
        #pragma unroll
        for (int j = 0; j < 8; j++)
            #pragma unroll
            for (int q = 0; q < 4; q++) acc[i][j][q] = 0.f;

    // per-lane ldmatrix offsets (80B-padded rows -> conflict-free)
    const uint32_t a_off = (uint32_t)(lid & 15) * ROWB + (uint32_t)(lid >> 4) * 16;
    const int b_nloc = (lid < 16) ? (lid & 7) : 8 + (lid & 7);
    const uint32_t b_off = (uint32_t)b_nloc * ROWB + (uint32_t)((lid >> 3) & 1) * 16;

    // stage loader: 6 cp.async of 16B per thread (3 arrays x 512 chunks)
    auto load_stage = [&](int s) {
        uint32_t buf = sb + (uint32_t)(s % NSTAGE) * STAGEB;
        int k0 = s * BK;
        #pragma unroll
        for (int i = 0; i < 6; i++) {
            int v = tid + i * 256;
            int arr = v >> 9;            // 0: Xhi, 1: Xlo, 2: Whi
            int idx = v & 511;
            int r = idx >> 2, c = idx & 3;
            uint32_t dst = buf + (uint32_t)arr * ARRB + (uint32_t)r * ROWB + (uint32_t)c * 16;
            const unsigned short* src;
            if (arr == 0)      src = g_Xhi + (size_t)(m0 + r) * DIM_D + k0 + c * 8;
            else if (arr == 1) src = g_Xlo + (size_t)(m0 + r) * DIM_D + k0 + c * 8;
            else               src = g_Whi + (size_t)(n0 + r) * DIM_D + k0 + c * 8;
            CP16(dst, src);
        }
    };

    load_stage(0); CP_COMMIT();
    load_stage(1); CP_COMMIT();

    for (int s = 0; s < KSTAGES; s++) {
        if (s < KSTAGES - 1) CP_WAIT1(); else CP_WAIT0();
        __syncthreads();
        if (s + 2 < KSTAGES) { load_stage(s + 2); CP_COMMIT(); }

        uint32_t buf = sb + (uint32_t)(s % NSTAGE) * STAGEB;
        #pragma unroll
        for (int kk = 0; kk < 2; kk++) {
            uint32_t koff = (uint32_t)kk * 32;
            uint32_t ra_h[2][4], ra_l[2][4];
            #pragma unroll
            for (int mt = 0; mt < 2; mt++) {
                uint32_t arow = (uint32_t)(wm * 32 + mt * 16) * ROWB + koff + a_off;
                ldsm_x4(ra_h[mt], buf + arow);
                ldsm_x4(ra_l[mt], buf + ARRB + arow);
            }
            #pragma unroll
            for (int half = 0; half < 2; half++) {
                uint32_t rb[2][4];
                #pragma unroll
                for (int g = 0; g < 2; g++)
                    ldsm_x4(rb[g], buf + 2 * ARRB +
                        (uint32_t)(wn * 64 + (half * 2 + g) * 16) * ROWB + koff + b_off);
                #pragma unroll
                for (int mt = 0; mt < 2; mt++)
                    #pragma unroll
                    for (int n4 = 0; n4 < 4; n4++) {
                        uint32_t b0 = rb[n4 >> 1][(n4 & 1) * 2];
                        uint32_t b1 = rb[n4 >> 1][(n4 & 1) * 2 + 1];
                        mma_fp16(acc[mt][half * 4 + n4], ra_h[mt], b0, b1);
                        mma_fp16(acc[mt][half * 4 + n4], ra_l[mt], b0, b1);
                    }
            }
        }
    }

    // Epilogue: bias add + float2 stores
    const int r0 = m0 + wm * 32 + (lid >> 2);
    const int cb = n0 + wn * 64 + (lid & 3) * 2;
    #pragma unroll
    for (int nt = 0; nt < 8; nt++) {
        float2 bv = *(const float2*)(bias + cb + nt * 8);
        #pragma unroll
        for (int mt = 0; mt < 2; mt++) {
            int r = r0 + mt * 16;
            float2 v0 = make_float2(acc[mt][nt][0] + bv.x, acc[mt][nt][1] + bv.y);
            float2 v1 = make_float2(acc[mt][nt][2] + bv.x, acc[mt][nt][3] + bv.y);
            *(float2*)(out + (size_t)r * DIM_N + cb + nt * 8) = v0;
            *(float2*)(out + (size_t)(r + 8) * DIM_N + cb + nt * 8) = v1;
        }
    }
}

// ---------------------------------------------------------------------------
// Launch
// ---------------------------------------------------------------------------
extern "C" void kernel_launch(void* const* d_in, const int* in_sizes, int n_in,
                              void* d_out, int out_size) {
    const float* x      = (const float*)d_in[0];
    const float* Aq     = (const float*)d_in[1];
    const float* Bq     = (const float*)d_in[2];
    const float* Av     = (const float*)d_in[3];
    const float* Bv     = (const float*)d_in[4];
    const float* qkvw   = (const float*)d_in[5];
    const float* qkvb   = (const float*)d_in[6];
    const float* logits = (const float*)d_in[7];
    const float* alpha  = (const float*)d_in[8];
    float* out = (float*)d_out;

    cudaFuncSetAttribute(k_gemm_mma, cudaFuncAttributeMaxDynamicSharedMemorySize, SMEM_TOTAL);

    k_sumsq    <<<40, 256>>>(Aq, Bq, Av, Bv);
    k_weights  <<<1, 32>>>(logits, alpha);
    k_convert_x<<<(BATCH_M * DIM_D / 4) / 256, 256>>>(x);
    k_weff     <<<dim3(DIM_D / 128, DIM_N / 16), 128>>>(Aq, Bq, Av, Bv, qkvw);
    k_gemm_mma <<<dim3(DIM_N / BN, BATCH_M / BM), 256, SMEM_TOTAL>>>(qkvb, out);
}

// round 5
// speedup vs baseline: 5.0711x; 1.5757x over previous
#include <cuda_runtime.h>
#include <cuda_fp16.h>
#include <math.h>
#include <stdint.h>

// Problem constants
#define BATCH_M   16384   // B*S
#define DIM_D     768
#define DIM_N     2304    // 3*D
#define NUM_T     10
#define RANK_R    16
#define SEG       (RANK_R * DIM_D)

// GEMM tiling
#define BM 128
#define BN 128
#define BK 32                      // fp16 elems per K stage
#define KSTAGES (DIM_D / BK)       // 24

// SMEM: 2 arrays per stage (Xh, Wh), rows padded to 80B
#define ROWB     80
#define ARRB     10240             // 128 rows * 80B
#define STAGEB   20480
#define NSTAGE   4
#define SMEM_TOTAL (NSTAGE * STAGEB)

// Device scratch (no cudaMalloc allowed)
__device__ float g_sumsq[40];
__device__ float g_wq[NUM_T];
__device__ float g_wv[NUM_T];
__device__ __align__(16) unsigned short g_Xh[(size_t)BATCH_M * DIM_D];
__device__ __align__(16) unsigned short g_Wh[(size_t)DIM_N * DIM_D];

// ---------------------------------------------------------------------------
// Helpers
// ---------------------------------------------------------------------------
__device__ __forceinline__ uint32_t smem_u32(const void* p) {
    uint32_t a;
    asm("{ .reg .u64 t; cvta.to.shared.u64 t, %1; cvt.u32.u64 %0, t; }" : "=r"(a) : "l"(p));
    return a;
}
#define CP16(dst, src) \
    asm volatile("cp.async.cg.shared.global [%0], [%1], 16;" :: "r"(dst), "l"(src))
#define CP_COMMIT() asm volatile("cp.async.commit_group;" ::: "memory")
#define CP_WAIT2()  asm volatile("cp.async.wait_group 2;"  ::: "memory")

__device__ __forceinline__ void ldsm_x4(uint32_t* r, uint32_t addr) {
    asm volatile("ldmatrix.sync.aligned.m8n8.x4.shared.b16 {%0,%1,%2,%3}, [%4];"
        : "=r"(r[0]), "=r"(r[1]), "=r"(r[2]), "=r"(r[3]) : "r"(addr));
}
__device__ __forceinline__ void mma_fp16(float* c, const uint32_t* a,
                                         uint32_t b0, uint32_t b1) {
    asm volatile("mma.sync.aligned.m16n8k16.row.col.f32.f16.f16.f32 "
        "{%0,%1,%2,%3},{%4,%5,%6,%7},{%8,%9},{%0,%1,%2,%3};"
        : "+f"(c[0]), "+f"(c[1]), "+f"(c[2]), "+f"(c[3])
        : "r"(a[0]), "r"(a[1]), "r"(a[2]), "r"(a[3]), "r"(b0), "r"(b1));
}

// ---------------------------------------------------------------------------
// Kernel 1: per-task Frobenius sum-of-squares
// ---------------------------------------------------------------------------
__global__ void k_sumsq(const float* __restrict__ Aq, const float* __restrict__ Bq,
                        const float* __restrict__ Av, const float* __restrict__ Bv) {
    int b = blockIdx.x;
    const float* base;
    switch (b / NUM_T) {
        case 0:  base = Aq; break;
        case 1:  base = Bq; break;
        case 2:  base = Av; break;
        default: base = Bv; break;
    }
    base += (b % NUM_T) * SEG;
    float s = 0.f;
    for (int i = threadIdx.x; i < SEG; i += blockDim.x) {
        float v = base[i];
        s += v * v;
    }
    __shared__ float red[256];
    red[threadIdx.x] = s;
    __syncthreads();
    for (int o = 128; o > 0; o >>= 1) {
        if (threadIdx.x < o) red[threadIdx.x] += red[threadIdx.x + o];
        __syncthreads();
    }
    if (threadIdx.x == 0) g_sumsq[b] = red[0];
}

// ---------------------------------------------------------------------------
// Kernel 2: softmax gate + fold alpha / norms into per-task weights
// ---------------------------------------------------------------------------
__global__ void k_weights(const float* __restrict__ logits,
                          const float* __restrict__ alpha) {
    if (threadIdx.x == 0 && blockIdx.x == 0) {
        float mx = -1e30f;
        for (int t = 0; t < NUM_T; t++) mx = fmaxf(mx, logits[t]);
        float e[NUM_T], se = 0.f;
        for (int t = 0; t < NUM_T; t++) { e[t] = expf(logits[t] - mx); se += e[t]; }
        for (int t = 0; t < NUM_T; t++) {
            float coef = (e[t] / se) * alpha[t];
            g_wq[t] = coef / (sqrtf(g_sumsq[t])      * sqrtf(g_sumsq[10 + t]) + 1e-8f);
            g_wv[t] = coef / (sqrtf(g_sumsq[20 + t]) * sqrtf(g_sumsq[30 + t]) + 1e-8f);
        }
    }
}

// ---------------------------------------------------------------------------
// Kernel 3: build fused weight W_eff -> fp16.
// Block = 128 threads: 16 e-rows x 128 d-cols. Weighted B staged in smem as
// [i][e]; deep unroll so LDGs are front-batched (high MLP).
// ---------------------------------------------------------------------------
__global__ __launch_bounds__(128)
void k_weff(const float* __restrict__ Aq, const float* __restrict__ Bq,
            const float* __restrict__ Av, const float* __restrict__ Bv,
            const float* __restrict__ qkvw) {
    const int d  = blockIdx.x * 128 + threadIdx.x;
    const int e0 = blockIdx.y * 16;
    const int tx = threadIdx.x;

    float acc[16];
    #pragma unroll
    for (int e = 0; e < 16; e++) acc[e] = 0.f;

    bool is_q = (e0 < DIM_D);
    bool is_v = (e0 >= 2 * DIM_D);
    if (is_q || is_v) {
        __shared__ __align__(16) float sB[NUM_T * RANK_R * 16];  // [i][e]
        const float* Am = is_q ? Aq : Av;
        const float* Bm = is_q ? Bq : Bv;
        int el0 = is_q ? e0 : (e0 - 2 * DIM_D);
        for (int idx = tx; idx < NUM_T * RANK_R * 16; idx += 128) {
            int i = idx >> 4, e = idx & 15;
            int t = i >> 4,  r = i & 15;
            float w = is_q ? g_wq[t] : g_wv[t];
            sB[idx] = w * Bm[((size_t)t * DIM_D + el0 + e) * RANK_R + r];
        }
        __syncthreads();

        const float4* sB4 = (const float4*)sB;
        #pragma unroll 16
        for (int i = 0; i < NUM_T * RANK_R; i++) {
            float a = __ldg(Am + (size_t)i * DIM_D + d);
            float4 b0 = sB4[i * 4 + 0];
            float4 b1 = sB4[i * 4 + 1];
            float4 b2 = sB4[i * 4 + 2];
            float4 b3 = sB4[i * 4 + 3];
            acc[0]  += a * b0.x;  acc[1]  += a * b0.y;
            acc[2]  += a * b0.z;  acc[3]  += a * b0.w;
            acc[4]  += a * b1.x;  acc[5]  += a * b1.y;
            acc[6]  += a * b1.z;  acc[7]  += a * b1.w;
            acc[8]  += a * b2.x;  acc[9]  += a * b2.y;
            acc[10] += a * b2.z;  acc[11] += a * b2.w;
            acc[12] += a * b3.x;  acc[13] += a * b3.y;
            acc[14] += a * b3.z;  acc[15] += a * b3.w;
        }
    }
    #pragma unroll
    for (int e = 0; e < 16; e++) {
        float val = qkvw[(size_t)(e0 + e) * DIM_D + d] + acc[e];
        g_Wh[(size_t)(e0 + e) * DIM_D + d] = __half_as_ushort(__float2half(val));
    }
}

// ---------------------------------------------------------------------------
// Kernel 3b: quantize X to fp16
// ---------------------------------------------------------------------------
__global__ void k_convert_x(const float* __restrict__ x) {
    size_t i = ((size_t)blockIdx.x * blockDim.x + threadIdx.x) * 4;
    float4 v = *(const float4*)(x + i);
    __half h0 = __float2half(v.x), h1 = __float2half(v.y),
           h2 = __float2half(v.z), h3 = __float2half(v.w);
    uint2 hh = make_uint2((uint32_t)__half_as_ushort(h0) | ((uint32_t)__half_as_ushort(h1) << 16),
                          (uint32_t)__half_as_ushort(h2) | ((uint32_t)__half_as_ushort(h3) << 16));
    *(uint2*)(g_Xh + i) = hh;
}

// ---------------------------------------------------------------------------
// Kernel 4: HMMA GEMM  out = Xh @ Wh^T + bias   (fp16, single product)
//   128x128 CTA tile, BK=32, 4-stage cp.async pipeline, 1 sync/stage.
// ---------------------------------------------------------------------------
__global__ __launch_bounds__(256, 2)
void k_gemm_mma(const float* __restrict__ bias, float* __restrict__ out) {
    extern __shared__ __align__(128) char smem[];
    const uint32_t sb = smem_u32(smem);
    const int tid = threadIdx.x;
    const int lid = tid & 31;
    const int wid = tid >> 5;
    const int wm = wid & 3;          // 4 warps in M, 32 rows each
    const int wn = wid >> 2;         // 2 warps in N, 64 cols each
    const int m0 = blockIdx.y * BM;
    const int n0 = blockIdx.x * BN;

    float acc[2][8][4];
    #pragma unroll
    for (int i = 0; i < 2; i++)
        #pragma unroll
        for (int j = 0; j < 8; j++)
            #pragma unroll
            for (int q = 0; q < 4; q++) acc[i][j][q] = 0.f;

    // per-lane ldmatrix offsets (80B-padded rows -> conflict-free)
    const uint32_t a_off = (uint32_t)(lid & 15) * ROWB + (uint32_t)(lid >> 4) * 16;
    const int b_nloc = (lid < 16) ? (lid & 7) : 8 + (lid & 7);
    const uint32_t b_off = (uint32_t)b_nloc * ROWB + (uint32_t)((lid >> 3) & 1) * 16;

    // stage loader: 4 cp.async of 16B per thread (2 arrays x 512 chunks)
    auto load_stage = [&](int s) {
        uint32_t buf = sb + (uint32_t)(s % NSTAGE) * STAGEB;
        int k0 = s * BK;
        #pragma unroll
        for (int i = 0; i < 4; i++) {
            int v = tid + i * 256;
            int arr = v >> 9;            // 0: Xh, 1: Wh
            int idx = v & 511;
            int r = idx >> 2, c = idx & 3;
            uint32_t dst = buf + (uint32_t)arr * ARRB + (uint32_t)r * ROWB + (uint32_t)c * 16;
            const unsigned short* src = arr == 0
                ? g_Xh + (size_t)(m0 + r) * DIM_D + k0 + c * 8
                : g_Wh + (size_t)(n0 + r) * DIM_D + k0 + c * 8;
            CP16(dst, src);
        }
    };

    load_stage(0); CP_COMMIT();
    load_stage(1); CP_COMMIT();
    load_stage(2); CP_COMMIT();

    for (int s = 0; s < KSTAGES; s++) {
        CP_WAIT2();                       // stage s resident
        __syncthreads();                  // all warps done with stage s-1
        if (s + 3 < KSTAGES) load_stage(s + 3);
        CP_COMMIT();                      // empty groups at tail keep count right

        uint32_t buf = sb + (uint32_t)(s % NSTAGE) * STAGEB;
        #pragma unroll
        for (int kk = 0; kk < 2; kk++) {
            uint32_t koff = (uint32_t)kk * 32;
            uint32_t ra[2][4];
            #pragma unroll
            for (int mt = 0; mt < 2; mt++)
                ldsm_x4(ra[mt], buf + (uint32_t)(wm * 32 + mt * 16) * ROWB + koff + a_off);
            #pragma unroll
            for (int half = 0; half < 2; half++) {
                uint32_t rb[2][4];
                #pragma unroll
                for (int g = 0; g < 2; g++)
                    ldsm_x4(rb[g], buf + ARRB +
                        (uint32_t)(wn * 64 + (half * 2 + g) * 16) * ROWB + koff + b_off);
                #pragma unroll
                for (int mt = 0; mt < 2; mt++)
                    #pragma unroll
                    for (int n4 = 0; n4 < 4; n4++) {
                        uint32_t b0 = rb[n4 >> 1][(n4 & 1) * 2];
                        uint32_t b1 = rb[n4 >> 1][(n4 & 1) * 2 + 1];
                        mma_fp16(acc[mt][half * 4 + n4], ra[mt], b0, b1);
                    }
            }
        }
    }

    // Epilogue: bias add + float2 stores
    const int r0 = m0 + wm * 32 + (lid >> 2);
    const int cb = n0 + wn * 64 + (lid & 3) * 2;
    #pragma unroll
    for (int nt = 0; nt < 8; nt++) {
        float2 bv = *(const float2*)(bias + cb + nt * 8);
        #pragma unroll
        for (int mt = 0; mt < 2; mt++) {
            int r = r0 + mt * 16;
            float2 v0 = make_float2(acc[mt][nt][0] + bv.x, acc[mt][nt][1] + bv.y);
            float2 v1 = make_float2(acc[mt][nt][2] + bv.x, acc[mt][nt][3] + bv.y);
            *(float2*)(out + (size_t)r * DIM_N + cb + nt * 8) = v0;
            *(float2*)(out + (size_t)(r + 8) * DIM_N + cb + nt * 8) = v1;
        }
    }
}

// ---------------------------------------------------------------------------
// Launch
// ---------------------------------------------------------------------------
extern "C" void kernel_launch(void* const* d_in, const int* in_sizes, int n_in,
                              void* d_out, int out_size) {
    const float* x      = (const float*)d_in[0];
    const float* Aq     = (const float*)d_in[1];
    const float* Bq     = (const float*)d_in[2];
    const float* Av     = (const float*)d_in[3];
    const float* Bv     = (const float*)d_in[4];
    const float* qkvw   = (const float*)d_in[5];
    const float* qkvb   = (const float*)d_in[6];
    const float* logits = (const float*)d_in[7];
    const float* alpha  = (const float*)d_in[8];
    float* out = (float*)d_out;

    cudaFuncSetAttribute(k_gemm_mma, cudaFuncAttributeMaxDynamicSharedMemorySize, SMEM_TOTAL);

    k_sumsq    <<<40, 256>>>(Aq, Bq, Av, Bv);
    k_weights  <<<1, 32>>>(logits, alpha);
    k_convert_x<<<(BATCH_M * DIM_D / 4) / 256, 256>>>(x);
    k_weff     <<<dim3(DIM_D / 128, DIM_N / 16), 128>>>(Aq, Bq, Av, Bv, qkvw);
    k_gemm_mma <<<dim3(DIM_N / BN, BATCH_M / BM), 256, SMEM_TOTAL>>>(qkvb, out);
}